// round 9
// baseline (speedup 1.0000x reference)
#include <cuda_runtime.h>
#include <cuda_fp16.h>
#include <math.h>
#include <stdint.h>

#define B_  2
#define T_  2048
#define D_  2048
#define NH_ 16
#define KH_ 4
#define H_  128

// Scratch (allocation-free rule: __device__ globals)
__device__ __half g_xqh [B_*T_*D_];        // Xq  fp16
__device__ __half g_xkvh[B_*T_*D_];        // Xkv fp16
__device__ __half g_wqt [NH_*H_*D_];       // Wq^T  fp16 [NHH][D]
__device__ __half g_wkt [KH_*H_*D_];       // Wk^T  fp16 [KHH][D]
__device__ __half g_wvt [KH_*H_*D_];       // Wv^T  fp16 [KHH][D]
__device__ __half g_wot [D_*NH_*H_];       // Wo^T  fp16 [D][NHH]
__device__ float  g_q  [B_*T_*NH_*H_];     // q proj fp32
__device__ float  g_k  [B_*T_*KH_*H_];     // k proj fp32
__device__ float  g_v  [B_*T_*KH_*H_];     // v proj fp32
__device__ __half g_qh [B_*T_*NH_*H_];     // q rope'd, scaled, fp16 (b,t,n,h)
__device__ __half g_kh [B_*T_*KH_*H_];     // k rope'd fp16 (b,t,k,h)
__device__ __half g_vt [B_*KH_*H_*T_];     // v fp16 transposed (b,k,h,t)
__device__ __half g_attn[B_*T_*NH_*H_];    // attn out fp16 (b,t,n,h)

__device__ __forceinline__ uint32_t f2h2(float lo, float hi) {
    __half2 h = __floats2half2_rn(lo, hi);
    return *(uint32_t*)&h;
}

__device__ __forceinline__ void cpasync16(void* dst, const void* src) {
    uint32_t d = (uint32_t)__cvta_generic_to_shared(dst);
    asm volatile("cp.async.cg.shared.global [%0], [%1], 16;\n" :: "r"(d), "l"(src));
}

__device__ __forceinline__ uint32_t smem_u32(const void* p) {
    return (uint32_t)__cvta_generic_to_shared(p);
}

__device__ __forceinline__ void mma16(float* c, const uint32_t* a, const uint32_t* b) {
    asm volatile(
        "mma.sync.aligned.m16n8k16.row.col.f32.f16.f16.f32 "
        "{%0,%1,%2,%3}, {%4,%5,%6,%7}, {%8,%9}, {%0,%1,%2,%3};\n"
        : "+f"(c[0]), "+f"(c[1]), "+f"(c[2]), "+f"(c[3])
        : "r"(a[0]), "r"(a[1]), "r"(a[2]), "r"(a[3]),
          "r"(b[0]), "r"(b[1]));
}

__device__ __forceinline__ void ldsm4(uint32_t& r0, uint32_t& r1,
                                      uint32_t& r2, uint32_t& r3, uint32_t addr) {
    asm volatile("ldmatrix.sync.aligned.m8n8.x4.shared.b16 {%0,%1,%2,%3}, [%4];"
                 : "=r"(r0), "=r"(r1), "=r"(r2), "=r"(r3) : "r"(addr));
}

// ---------------------------------------------------------------------------
// Aux kernels: cvt fp32->fp16, transposes
// ---------------------------------------------------------------------------
__global__ void cvt16(const float* __restrict__ s, __half2* __restrict__ d) {
    int i = blockIdx.x * 256 + threadIdx.x;
    float4 a = ((const float4*)s)[i];
    d[2*i]   = __floats2half2_rn(a.x, a.y);
    d[2*i+1] = __floats2half2_rn(a.z, a.w);
}

__global__ void tr16(const float* __restrict__ src, __half* __restrict__ dst,
                     int R, int C) {
    __shared__ float tile[32][33];
    int c0 = blockIdx.x * 32, r0 = blockIdx.y * 32;
    int tx = threadIdx.x & 31, ty = threadIdx.x >> 5;
#pragma unroll
    for (int i = 0; i < 32; i += 8)
        tile[ty + i][tx] = src[(size_t)(r0 + ty + i) * C + c0 + tx];
    __syncthreads();
#pragma unroll
    for (int i = 0; i < 32; i += 8)
        dst[(size_t)(c0 + ty + i) * R + r0 + tx] = __float2half_rn(tile[tx][ty + i]);
}

__global__ void trv(const float* __restrict__ v, __half* __restrict__ vt) {
    __shared__ float tile[32][33];
    int bk = blockIdx.z, b = bk >> 2, kh = bk & 3;
    int t0 = blockIdx.x * 32, h0 = blockIdx.y * 32;
    int tx = threadIdx.x & 31, ty = threadIdx.x >> 5;
#pragma unroll
    for (int i = 0; i < 32; i += 8)
        tile[ty + i][tx] =
            v[(((size_t)(b * T_ + t0 + ty + i)) * KH_ + kh) * H_ + h0 + tx];
    __syncthreads();
#pragma unroll
    for (int i = 0; i < 32; i += 8)
        vt[((size_t)(b * KH_ + kh) * H_ + h0 + ty + i) * T_ + t0 + tx] =
            __float2half_rn(tile[tx][ty + i]);
}

// ---------------------------------------------------------------------------
// RoPE: fp32 in -> fp16 out (q also scaled). rope_q grid (M, 4): 4 heads/block.
// ---------------------------------------------------------------------------
__global__ void rope_q16(const float* __restrict__ x, __half* __restrict__ y,
                         const int* __restrict__ pos, float scale) {
    int token = blockIdx.x;
    int ng = blockIdx.y * 4;
    int i = threadIdx.x;  // 0..63
    double ts = exp(((double)i / 64.0) * 9.210340371976182736);
    float p = (float)pos[token];
    float angf = p / (float)ts;
    double s_, c_;
    sincos((double)angf, &s_, &c_);
    float s = (float)s_, c = (float)c_;
    const float* base = x + (size_t)token * NH_ * H_;
    __half* dst = y + (size_t)token * NH_ * H_;
#pragma unroll
    for (int n = ng; n < ng + 4; n++) {
        float x1 = base[n * H_ + i];
        float x2 = base[n * H_ + i + 64];
        dst[n * H_ + i]      = __float2half_rn((x1 * c - x2 * s) * scale);
        dst[n * H_ + i + 64] = __float2half_rn((x2 * c + x1 * s) * scale);
    }
}

__global__ void rope_k16(const float* __restrict__ x, __half* __restrict__ y,
                         const int* __restrict__ pos) {
    int token = blockIdx.x;
    int i = threadIdx.x;
    double ts = exp(((double)i / 64.0) * 9.210340371976182736);
    float p = (float)pos[token];
    float angf = p / (float)ts;
    double s_, c_;
    sincos((double)angf, &s_, &c_);
    float s = (float)s_, c = (float)c_;
    const float* base = x + (size_t)token * KH_ * H_;
    __half* dst = y + (size_t)token * KH_ * H_;
#pragma unroll
    for (int n = 0; n < KH_; n++) {
        float x1 = base[n * H_ + i];
        float x2 = base[n * H_ + i + 64];
        dst[n * H_ + i]      = __float2half_rn(x1 * c - x2 * s);
        dst[n * H_ + i + 64] = __float2half_rn(x2 * c + x1 * s);
    }
}

// ---------------------------------------------------------------------------
// FP16 tensor-core GEMM (R7, unchanged): C[M,Nc]fp32 = A fp16 @ Bt fp16^T
// ---------------------------------------------------------------------------
#define GST 20

__device__ __forceinline__
void gemm16_body(const uint32_t* __restrict__ A, const uint32_t* __restrict__ Bt,
                 float* __restrict__ C, int M, int Nc, int Kd) {
    __shared__ uint32_t As[2][128 * GST];
    __shared__ uint32_t Bs[2][128 * GST];
    int tid  = threadIdx.x;
    int brow = blockIdx.y * 128, bcol = blockIdx.x * 128;
    int warp = tid >> 5, lane = tid & 31;
    int mw = (warp >> 2) * 64, nw = (warp & 3) * 32;
    int lr = lane >> 2, lc = lane & 3;
    int KW = Kd >> 1;

    float acc[4][4][4];
#pragma unroll
    for (int mi = 0; mi < 4; mi++)
#pragma unroll
        for (int ni = 0; ni < 4; ni++)
#pragma unroll
            for (int j = 0; j < 4; j++) acc[mi][ni][j] = 0.f;

    const int nkt = Kd >> 5;

    auto load_stage = [&](int kt, int buf) {
        int kw0 = kt * 16;
#pragma unroll
        for (int u = 0; u < 2; u++) {
            int c = tid + 256 * u;
            int row = c >> 2, w4 = (c & 3) * 4;
            cpasync16(&As[buf][row * GST + w4],
                      &A[(size_t)(brow + row) * KW + kw0 + w4]);
            cpasync16(&Bs[buf][row * GST + w4],
                      &Bt[(size_t)(bcol + row) * KW + kw0 + w4]);
        }
    };

    load_stage(0, 0);
    asm volatile("cp.async.commit_group;\n");

    for (int kt = 0; kt < nkt; kt++) {
        int buf = kt & 1;
        if (kt + 1 < nkt) {
            load_stage(kt + 1, buf ^ 1);
            asm volatile("cp.async.commit_group;\n");
            asm volatile("cp.async.wait_group 1;\n");
        } else {
            asm volatile("cp.async.wait_group 0;\n");
        }
        __syncthreads();

#pragma unroll
        for (int ks = 0; ks < 2; ks++) {
            uint32_t af[4][4], bf[4][2];
#pragma unroll
            for (int mi = 0; mi < 4; mi++) {
                const uint32_t* p = &As[buf][(mw + mi * 16 + lr) * GST + ks * 8 + lc];
                af[mi][0] = p[0];
                af[mi][1] = p[8 * GST];
                af[mi][2] = p[4];
                af[mi][3] = p[8 * GST + 4];
            }
#pragma unroll
            for (int ni = 0; ni < 4; ni++) {
                const uint32_t* p = &Bs[buf][(nw + ni * 8 + lr) * GST + ks * 8 + lc];
                bf[ni][0] = p[0];
                bf[ni][1] = p[4];
            }
#pragma unroll
            for (int mi = 0; mi < 4; mi++)
#pragma unroll
                for (int ni = 0; ni < 4; ni++)
                    mma16(acc[mi][ni], af[mi], bf[ni]);
        }
        __syncthreads();
    }

#pragma unroll
    for (int mi = 0; mi < 4; mi++) {
#pragma unroll
        for (int ni = 0; ni < 4; ni++) {
            int r0 = brow + mw + mi * 16 + lr;
            int cc = bcol + nw + ni * 8 + lc * 2;
            *(float2*)&C[(size_t)r0 * Nc + cc] =
                make_float2(acc[mi][ni][0], acc[mi][ni][1]);
            *(float2*)&C[(size_t)(r0 + 8) * Nc + cc] =
                make_float2(acc[mi][ni][2], acc[mi][ni][3]);
        }
    }
}

__global__ __launch_bounds__(256, 2)
void gemm16(const uint32_t* __restrict__ A, const uint32_t* __restrict__ Bt,
            float* __restrict__ C, int M, int Nc, int Kd) {
    gemm16_body(A, Bt, C, M, Nc, Kd);
}

__global__ __launch_bounds__(256, 2)
void gemm16_kv(const uint32_t* __restrict__ A,
               const uint32_t* __restrict__ B0, const uint32_t* __restrict__ B1,
               float* __restrict__ C0, float* __restrict__ C1,
               int M, int Nc, int Kd) {
    gemm16_body(A, blockIdx.z ? B1 : B0, blockIdx.z ? C1 : C0, M, Nc, Kd);
}

// ---------------------------------------------------------------------------
// FP16 flash attention: Q tile 128, KV tile 128, causal, GQA.
// P kept in registers (C-frag -> A-frag direct map); K/V via ldmatrix.x4.
// ---------------------------------------------------------------------------
#define KST  68
#define VSTW 68
#define FA_SMEM ((2*128*KST + 2*128*VSTW) * 4)

__global__ __launch_bounds__(256, 1)
void flash16(const uint32_t* __restrict__ qh, const uint32_t* __restrict__ kk,
             const uint32_t* __restrict__ vt, uint32_t* __restrict__ o) {
    extern __shared__ uint32_t sm_u[];
    uint32_t* Ks = sm_u;                     // [2][128*KST]
    uint32_t* Vs = Ks + 2 * 128 * KST;       // [2][128*VSTW]

    int qt = (int)gridDim.x - 1 - (int)blockIdx.x;
    int n  = blockIdx.y;
    int b  = blockIdx.z;
    int khd = n >> 2;
    int tid = threadIdx.x, warp = tid >> 5, lane = tid & 31;
    int lr = lane >> 2, lc = lane & 3;
    int q0 = qt * 128;

    // ldmatrix lane constants: lanes 8m+r supply row r of matrix m
    int rowsel = ((lane >> 4) & 1) * 8 + (lane & 7);  // +8 rows for m2/m3
    int offw   = ((lane >> 3) & 1) * 4;               // +16B for m1/m3

    // ---- Q fragments: stage 64 rows at a time into Ks[0] ----
    uint32_t qf[8][4];
#pragma unroll
    for (int pass = 0; pass < 2; pass++) {
#pragma unroll
        for (int u = 0; u < 4; u++) {
            int f = tid + 256 * u;
            int r = f >> 4, w4 = (f & 15) * 4;
            *(uint4*)(Ks + r * KST + w4) = *(const uint4*)(qh +
                ((size_t)((b * T_ + q0 + pass * 64 + r) * NH_ + n) << 6) + w4);
        }
        __syncthreads();
        if ((warp >> 2) == pass) {
            int mr = (warp & 3) * 16;
#pragma unroll
            for (int hs = 0; hs < 8; hs++) {
                const uint32_t* p = Ks + (mr + lr) * KST + hs * 8 + lc;
                qf[hs][0] = p[0];
                qf[hs][1] = p[8 * KST];
                qf[hs][2] = p[4];
                qf[hs][3] = p[8 * KST + 4];
            }
        }
        __syncthreads();
    }

    float m_[2] = {-1e30f, -1e30f};
    float l_[2] = {0.f, 0.f};
    float oacc[16][4];
#pragma unroll
    for (int ns = 0; ns < 16; ns++)
#pragma unroll
        for (int j = 0; j < 4; j++) oacc[ns][j] = 0.f;

    int row0 = q0 + warp * 16 + lr;
    int njt = qt + 1;

    auto load_kv = [&](int jt, int bufsel) {
        int s0 = jt * 128;
        uint32_t* Kd = Ks + bufsel * 128 * KST;
        uint32_t* Vd = Vs + bufsel * 128 * VSTW;
#pragma unroll
        for (int u = 0; u < 8; u++) {
            int f = tid + 256 * u;
            int r = f >> 4, w4 = (f & 15) * 4;
            cpasync16(Kd + r * KST + w4,
                      kk + ((size_t)((b * T_ + s0 + r) * KH_ + khd) << 6) + w4);
            cpasync16(Vd + r * VSTW + w4,
                      vt + ((((size_t)(b * KH_ + khd) * H_ + r) * T_ + s0) >> 1) + w4);
        }
    };

    load_kv(0, 0);
    asm volatile("cp.async.commit_group;\n");

    for (int jt = 0; jt < njt; jt++) {
        int buf = jt & 1;
        if (jt + 1 < njt) {
            load_kv(jt + 1, buf ^ 1);
            asm volatile("cp.async.commit_group;\n");
            asm volatile("cp.async.wait_group 1;\n");
        } else {
            asm volatile("cp.async.wait_group 0;\n");
        }
        __syncthreads();

        const uint32_t* Kb = Ks + buf * 128 * KST;
        const uint32_t* Vb = Vs + buf * 128 * VSTW;
        int s0 = jt * 128;

        // ---- S = Q K^T (ldmatrix.x4: 2 n-frags per load) ----
        float s_[16][4];
#pragma unroll
        for (int ns = 0; ns < 16; ns++)
#pragma unroll
            for (int j = 0; j < 4; j++) s_[ns][j] = 0.f;

        uint32_t kb0 = smem_u32(Kb) + (uint32_t)(rowsel * KST + offw) * 4;
#pragma unroll
        for (int hs = 0; hs < 8; hs++) {
#pragma unroll
            for (int np = 0; np < 8; np++) {
                uint32_t b0, b1, b2, b3;
                ldsm4(b0, b1, b2, b3,
                      kb0 + (uint32_t)(16 * np * KST + hs * 8) * 4);
                uint32_t bfa[2] = {b0, b1}, bfb[2] = {b2, b3};
                mma16(s_[2 * np],     qf[hs], bfa);
                mma16(s_[2 * np + 1], qf[hs], bfb);
            }
        }

        // ---- causal mask (diagonal tile only) ----
        if (jt == qt) {
#pragma unroll
            for (int ns = 0; ns < 16; ns++) {
                int col = s0 + ns * 8 + 2 * lc;
                if (col > row0)     s_[ns][0] = -1e30f;
                if (col + 1 > row0) s_[ns][1] = -1e30f;
                if (col > row0 + 8)     s_[ns][2] = -1e30f;
                if (col + 1 > row0 + 8) s_[ns][3] = -1e30f;
            }
        }

        // ---- online softmax; P packed straight into A-frag registers ----
        float mx0 = -1e30f, mx1 = -1e30f;
#pragma unroll
        for (int ns = 0; ns < 16; ns++) {
            mx0 = fmaxf(mx0, fmaxf(s_[ns][0], s_[ns][1]));
            mx1 = fmaxf(mx1, fmaxf(s_[ns][2], s_[ns][3]));
        }
        mx0 = fmaxf(mx0, __shfl_xor_sync(0xffffffffu, mx0, 1));
        mx0 = fmaxf(mx0, __shfl_xor_sync(0xffffffffu, mx0, 2));
        mx1 = fmaxf(mx1, __shfl_xor_sync(0xffffffffu, mx1, 1));
        mx1 = fmaxf(mx1, __shfl_xor_sync(0xffffffffu, mx1, 2));
        float mn0 = fmaxf(m_[0], mx0), mn1 = fmaxf(m_[1], mx1);
        float a0 = __expf(m_[0] - mn0), a1 = __expf(m_[1] - mn1);
        float sum0 = 0.f, sum1 = 0.f;
        uint32_t pf[16][2];
#pragma unroll
        for (int ns = 0; ns < 16; ns++) {
            float p0 = __expf(s_[ns][0] - mn0);
            float p1 = __expf(s_[ns][1] - mn0);
            float p2 = __expf(s_[ns][2] - mn1);
            float p3 = __expf(s_[ns][3] - mn1);
            sum0 += p0 + p1;
            sum1 += p2 + p3;
            pf[ns][0] = f2h2(p0, p1);   // rows lr   : a0/a2 source
            pf[ns][1] = f2h2(p2, p3);   // rows lr+8 : a1/a3 source
        }
        sum0 += __shfl_xor_sync(0xffffffffu, sum0, 1);
        sum0 += __shfl_xor_sync(0xffffffffu, sum0, 2);
        sum1 += __shfl_xor_sync(0xffffffffu, sum1, 1);
        sum1 += __shfl_xor_sync(0xffffffffu, sum1, 2);
        l_[0] = l_[0] * a0 + sum0;
        l_[1] = l_[1] * a1 + sum1;
        m_[0] = mn0; m_[1] = mn1;

#pragma unroll
        for (int ns = 0; ns < 16; ns++) {
            oacc[ns][0] *= a0; oacc[ns][1] *= a0;
            oacc[ns][2] *= a1; oacc[ns][3] *= a1;
        }

        // ---- O += P V (P from registers, V via ldmatrix.x4) ----
        uint32_t vb0 = smem_u32(Vb) + (uint32_t)(rowsel * VSTW + offw) * 4;
#pragma unroll
        for (int ks = 0; ks < 8; ks++) {
            uint32_t af[4] = {pf[2 * ks][0], pf[2 * ks][1],
                              pf[2 * ks + 1][0], pf[2 * ks + 1][1]};
#pragma unroll
            for (int np = 0; np < 8; np++) {
                uint32_t v0, v1, v2, v3;
                ldsm4(v0, v1, v2, v3,
                      vb0 + (uint32_t)(16 * np * VSTW + ks * 8) * 4);
                uint32_t bfa[2] = {v0, v1}, bfb[2] = {v2, v3};
                mma16(oacc[2 * np],     af, bfa);
                mma16(oacc[2 * np + 1], af, bfb);
            }
        }
        __syncthreads();
    }

    // ---- epilogue: normalize, store fp16 (b,t,n,h) ----
    float inv0 = 1.f / l_[0], inv1 = 1.f / l_[1];
    size_t wb0 = ((size_t)((b * T_ + row0) * NH_ + n) << 6);
    size_t wb1 = ((size_t)((b * T_ + row0 + 8) * NH_ + n) << 6);
#pragma unroll
    for (int ns = 0; ns < 16; ns++) {
        o[wb0 + ns * 4 + lc] = f2h2(oacc[ns][0] * inv0, oacc[ns][1] * inv0);
        o[wb1 + ns * 4 + lc] = f2h2(oacc[ns][2] * inv1, oacc[ns][3] * inv1);
    }
}

// ---------------------------------------------------------------------------
extern "C" void kernel_launch(void* const* d_in, const int* in_sizes, int n_in,
                              void* d_out, int out_size) {
    const float* Xq   = (const float*)d_in[0];
    const float* Xkv  = (const float*)d_in[1];
    const int*   qpos = (const int*)  d_in[2];
    const int*   kpos = (const int*)  d_in[3];
    const float* Wq   = (const float*)d_in[4];
    const float* Wk   = (const float*)d_in[5];
    const float* Wv   = (const float*)d_in[6];
    const float* Wo   = (const float*)d_in[7];
    float* out = (float*)d_out;

    __half *xqh, *xkvh, *wqt, *wkt, *wvt, *wot, *qh, *kh, *vt, *attn;
    float *pq, *pk, *pv;
    cudaGetSymbolAddress((void**)&xqh,  g_xqh);
    cudaGetSymbolAddress((void**)&xkvh, g_xkvh);
    cudaGetSymbolAddress((void**)&wqt,  g_wqt);
    cudaGetSymbolAddress((void**)&wkt,  g_wkt);
    cudaGetSymbolAddress((void**)&wvt,  g_wvt);
    cudaGetSymbolAddress((void**)&wot,  g_wot);
    cudaGetSymbolAddress((void**)&pq,   g_q);
    cudaGetSymbolAddress((void**)&pk,   g_k);
    cudaGetSymbolAddress((void**)&pv,   g_v);
    cudaGetSymbolAddress((void**)&qh,   g_qh);
    cudaGetSymbolAddress((void**)&kh,   g_kh);
    cudaGetSymbolAddress((void**)&vt,   g_vt);
    cudaGetSymbolAddress((void**)&attn, g_attn);

    const int M = B_ * T_;  // 4096
    const int NHH = NH_ * H_, KHH = KH_ * H_;
    const float scale = 0.08838834764831845f; // 1/sqrt(128)

    // inputs -> fp16
    cvt16<<<(B_*T_*D_) / 1024, 256>>>(Xq,  (__half2*)xqh);
    cvt16<<<(B_*T_*D_) / 1024, 256>>>(Xkv, (__half2*)xkvh);
    // weights -> fp16 transposed
    tr16<<<dim3(NHH / 32, D_ / 32), 256>>>(Wq, wqt, D_, NHH);
    tr16<<<dim3(KHH / 32, D_ / 32), 256>>>(Wk, wkt, D_, KHH);
    tr16<<<dim3(KHH / 32, D_ / 32), 256>>>(Wv, wvt, D_, KHH);
    tr16<<<dim3(D_ / 32, NHH / 32), 256>>>(Wo, wot, NHH, D_);

    // projections
    gemm16<<<dim3(NHH / 128, M / 128), 256>>>(
        (const uint32_t*)xqh, (const uint32_t*)wqt, pq, M, NHH, D_);
    gemm16_kv<<<dim3(KHH / 128, M / 128, 2), 256>>>(
        (const uint32_t*)xkvh, (const uint32_t*)wkt, (const uint32_t*)wvt,
        pk, pv, M, KHH, D_);

    // rope (fp32 -> fp16), V transpose
    rope_q16<<<dim3(M, 4), 64>>>(pq, qh, qpos, scale);
    rope_k16<<<M, 64>>>(pk, kh, kpos);
    trv<<<dim3(T_ / 32, H_ / 32, B_ * KH_), 256>>>(pv, vt);

    // flash attention (fp16 mma.sync, KV tile 128, P-in-regs + ldmatrix)
    cudaFuncSetAttribute(flash16,
                         cudaFuncAttributeMaxDynamicSharedMemorySize, FA_SMEM);
    flash16<<<dim3(T_ / 128, NH_, B_), 256, FA_SMEM>>>(
        (const uint32_t*)qh, (const uint32_t*)kh, (const uint32_t*)vt,
        (uint32_t*)attn);

    // output projection
    gemm16<<<dim3(D_ / 128, M / 128), 256>>>(
        (const uint32_t*)attn, (const uint32_t*)wot, out, M, D_, NHH);
}